// round 8
// baseline (speedup 1.0000x reference)
#include <cuda_runtime.h>
#include <cstdint>

// Single wave: 148 SMs x 4 blocks (__launch_bounds__(256,4) -> <=64 regs,
// room for a 2-pair software-pipelined load buffer) = 592 blocks.
// Neg split ~64:8:1 across levels; last 3 blocks do the pos gather.
// Finalize fused via last-block atomic ticket.
#define NBLK0 516
#define NBLK1 65
#define NBLK2 8
#define NEG_BLKS (NBLK0 + NBLK1 + NBLK2)   // 589
#define GRID_TOT (NEG_BLKS + 3)            // 592
#define THREADS 256

// Per-block neg partials [num,den]; pos partials [sum_w, sum_lw] per (level,b).
__device__ double g_partial[2 * NEG_BLKS];
__device__ double g_pos[2 * 24];
__device__ unsigned int g_count;           // zero-init; reset by reducer each launch

__device__ __forceinline__ float ex2f_(float x) {
    float r; asm("ex2.approx.f32 %0, %1;" : "=f"(r) : "f"(x)); return r;
}
__device__ __forceinline__ float rcpf_(float x) {
    float r; asm("rcp.approx.f32 %0, %1;" : "=f"(r) : "f"(x)); return r;
}
__device__ __forceinline__ float lg2f_(float x) {
    float r; asm("lg2.approx.f32 %0, %1;" : "=f"(r) : "f"(x)); return r;
}
__device__ __forceinline__ float tanhf_(float x) {
    float r; asm("tanh.approx.f32 %0, %1;" : "=f"(r) : "f"(x)); return r;
}

#define LOG2E 1.4426950408889634f
#define LN2   0.6931471805599453f

__device__ __forceinline__ double warp_red(double v) {
    #pragma unroll
    for (int off = 16; off > 0; off >>= 1)
        v += __shfl_down_sync(0xFFFFFFFFu, v, off);
    return v;
}

// Per-element neg contribution, 2 MUFU + ~7 FMA-class, branch-free:
//   h = tanh(x/2); p = 0.5+0.5h; q = 1-p = 0.5-0.5h
//   softplus(x) = -ln(q) = -ln2*lg2(q)   [the -ln2 scale applied at finalize]
//   prob_gt is exactly +-1  =>  mask = 0.5 - 0.5*g  (1 FMA, no SETP/SEL)
__device__ __forceinline__ void neg_elem(float x, float g, float& fn, float& fd) {
    float h = tanhf_(0.5f * x);
    float q = fmaf(-0.5f, h, 0.5f);
    float p = fmaf(0.5f, h, 0.5f);
    float l = lg2f_(q);
    float mask = fmaf(-0.5f, g, 0.5f);
    float w = p * p * mask;
    fn = fmaf(l, w, fn);    // accumulates lg2-scaled (negated at finalize)
    fd += w;
}

__device__ __forceinline__ void neg_quad(const float4& x, const float4& g,
                                         float& fn, float& fd) {
    neg_elem(x.x, g.x, fn, fd);
    neg_elem(x.y, g.y, fn, fd);
    neg_elem(x.z, g.z, fn, fd);
    neg_elem(x.w, g.w, fn, fd);
}

__global__ __launch_bounds__(THREADS, 4)
void main_kernel(const float* __restrict__ lg0, const float* __restrict__ lg1,
                 const float* __restrict__ lg2,
                 const float* __restrict__ pg0, const float* __restrict__ pg1,
                 const float* __restrict__ pg2,
                 const int* __restrict__ c0, const int* __restrict__ c1,
                 const int* __restrict__ c2,
                 int n0, int n1, int n2 /* float4 counts */,
                 float* __restrict__ out) {
    int blk = blockIdx.x;

    if (blk >= NEG_BLKS) {
        // ---------------- pos gather: one block per level ----------------
        // 8 warps = 8 batches; each lane handles m = lane + 32j, j=0..3.
        int level = blk - NEG_BLKS;
        const int* cd; const float* lg; int D;
        if (level == 0)      { cd = c0; lg = lg0; D = 96; }
        else if (level == 1) { cd = c1; lg = lg1; D = 48; }
        else                 { cd = c2; lg = lg2; D = 24; }
        int b = threadIdx.x >> 5;     // warp id = batch
        int lane = threadIdx.x & 31;
        double sw = 0.0, slw = 0.0;
        #pragma unroll
        for (int j = 0; j < 4; j++) {
            int m = lane + 32 * j;
            const int4 row = *(const int4*)(cd + ((b * 128 + m) << 2));
            if (row.x > -1) {
                int d = max(row.y, 0), h = max(row.z, 0), w = max(row.w, 0);
                int idx = (((b * 2 + row.x) * D + d) * D + h) * D + w;
                float x = __ldg(lg + idx);
                float t = ex2f_(x * LOG2E);
                float u = 1.0f + t;
                float r = rcpf_(u);            // == 1 - sigmoid(x) exactly
                float wq = r * r;
                float ls = x - LN2 * lg2f_(u); // logsigmoid(x)
                sw += (double)wq;
                slw += (double)(ls * wq);
            }
        }
        sw = warp_red(sw);
        slw = warp_red(slw);
        if (lane == 0) {
            g_pos[2 * (level * 8 + b) + 0] = sw;
            g_pos[2 * (level * 8 + b) + 1] = slw;
        }
    } else {
        // -------- neg reduction: 2 sub-streams, depth-1 prefetch of both --------
        const float4* lg; const float4* pg;
        int n, nb, lb;
        if (blk < NBLK0) {
            lg = (const float4*)lg0; pg = (const float4*)pg0; n = n0; nb = NBLK0; lb = blk;
        } else if (blk < NBLK0 + NBLK1) {
            lg = (const float4*)lg1; pg = (const float4*)pg1; n = n1; nb = NBLK1; lb = blk - NBLK0;
        } else {
            lg = (const float4*)lg2; pg = (const float4*)pg2; n = n2; nb = NBLK2; lb = blk - (NBLK0 + NBLK1);
        }

        float fn = 0.0f, fd = 0.0f;
        int stride = nb * THREADS;
        int i = lb * THREADS + threadIdx.x;

        if (i < n) {
            // prologue: load first pair of pairs
            float4 xa = lg[i], ga = pg[i];
            bool hasB = (i + stride) < n;
            float4 xb, gb;
            if (hasB) { xb = lg[i + stride]; gb = pg[i + stride]; }

            // steady state: prefetch next two pairs, compute current two
            while (i + 2 * stride < n) {
                int j = i + 2 * stride;
                float4 xa2 = lg[j], ga2 = pg[j];
                bool hasB2 = (j + stride) < n;
                float4 xb2, gb2;
                if (hasB2) { xb2 = lg[j + stride]; gb2 = pg[j + stride]; }

                neg_quad(xa, ga, fn, fd);
                neg_quad(xb, gb, fn, fd);   // hasB guaranteed true here

                xa = xa2; ga = ga2; xb = xb2; gb = gb2; hasB = hasB2; i = j;
            }
            // epilogue
            neg_quad(xa, ga, fn, fd);
            if (hasB) neg_quad(xb, gb, fn, fd);
        }
        double num = (double)fn;
        double den = (double)fd;

        num = warp_red(num);
        den = warp_red(den);
        __shared__ double s_num[THREADS / 32];
        __shared__ double s_den[THREADS / 32];
        int lane = threadIdx.x & 31, wid = threadIdx.x >> 5;
        if (lane == 0) { s_num[wid] = num; s_den[wid] = den; }
        __syncthreads();
        if (wid == 0) {
            double vn = (lane < THREADS / 32) ? s_num[lane] : 0.0;
            double vd = (lane < THREADS / 32) ? s_den[lane] : 0.0;
            vn = warp_red(vn);
            vd = warp_red(vd);
            if (lane == 0) {
                g_partial[2 * blockIdx.x + 0] = vn;
                g_partial[2 * blockIdx.x + 1] = vd;
            }
        }
    }

    // ---------------- last-block fused finalize ----------------
    __shared__ bool is_last;
    __syncthreads();                    // block's global writes done
    if (threadIdx.x == 0) {
        __threadfence();                // publish this block's partials device-wide
        unsigned int t = atomicAdd(&g_count, 1u);
        is_last = (t == GRID_TOT - 1);
    }
    __syncthreads();
    if (!is_last) return;
    __threadfence();                    // acquire all published partials

    int tid = threadIdx.x;
    double a0 = 0, a1 = 0, a2 = 0, a3 = 0, a4 = 0, a5 = 0;
    for (int b = tid; b < NEG_BLKS; b += THREADS) {
        double nu = g_partial[2 * b + 0];
        double de = g_partial[2 * b + 1];
        if (b < NBLK0)              { a0 += nu; a1 += de; }
        else if (b < NBLK0 + NBLK1) { a2 += nu; a3 += de; }
        else                        { a4 += nu; a5 += de; }
    }
    a0 = warp_red(a0); a1 = warp_red(a1); a2 = warp_red(a2);
    a3 = warp_red(a3); a4 = warp_red(a4); a5 = warp_red(a5);
    __shared__ double s_part[THREADS / 32][6];
    int lane = tid & 31, wid = tid >> 5;
    if (lane == 0) {
        s_part[wid][0] = a0; s_part[wid][1] = a1; s_part[wid][2] = a2;
        s_part[wid][3] = a3; s_part[wid][4] = a4; s_part[wid][5] = a5;
    }
    __syncthreads();
    if (tid == 0) {
        double acc[6] = {0, 0, 0, 0, 0, 0};
        #pragma unroll
        for (int w = 0; w < THREADS / 32; w++)
            #pragma unroll
            for (int k = 0; k < 6; k++) acc[k] += s_part[w][k];
        // num accumulated lg2(1-p)*w; softplus = -ln2 * lg2(1-p)
        double neg = (-(double)LN2) * (acc[0] / acc[1] + acc[2] / acc[3] + acc[4] / acc[5]);
        double pos = 0.0;
        #pragma unroll
        for (int g = 0; g < 24; g++) {
            double sw = g_pos[2 * g + 0];
            double slw = g_pos[2 * g + 1];
            pos += -slw / ((sw > 0.0) ? sw : 1.0);
        }
        out[0] = (float)pos;
        out[1] = (float)neg;
        out[2] = 1.0f;
        out[3] = 1.0f;
        g_count = 0;                    // reset for next graph replay
    }
}

// ---------------------------------------------------------------------------
// Inputs classified by element count (robust to interleaved-vs-grouped order):
// big arrays appear twice per level (logits first, then prob_gt); 4096-elem
// int arrays are coord0..2 in level order. Output: 4 f32 [pos, neg, 1, 1].
// ---------------------------------------------------------------------------
extern "C" void kernel_launch(void* const* d_in, const int* in_sizes, int n_in,
                              void* d_out, int out_size) {
    const int LVL_ELEMS[3] = {8 * 2 * 96 * 96 * 96,
                              8 * 2 * 48 * 48 * 48,
                              8 * 2 * 24 * 24 * 24};
    const float* lg[3] = {nullptr, nullptr, nullptr};
    const float* pg[3] = {nullptr, nullptr, nullptr};
    const int*   cd[3] = {nullptr, nullptr, nullptr};
    int n_coord = 0;

    for (int i = 0; i < n_in; i++) {
        int sz = in_sizes[i];
        if (sz == 8 * 128 * 4) {
            if (n_coord < 3) cd[n_coord++] = (const int*)d_in[i];
            continue;
        }
        for (int l = 0; l < 3; l++) {
            if (sz == LVL_ELEMS[l]) {
                if (!lg[l])      lg[l] = (const float*)d_in[i];
                else if (!pg[l]) pg[l] = (const float*)d_in[i];
                break;
            }
        }
    }

    float* out = (float*)d_out;
    main_kernel<<<GRID_TOT, THREADS>>>(lg[0], lg[1], lg[2],
                                       pg[0], pg[1], pg[2],
                                       cd[0], cd[1], cd[2],
                                       LVL_ELEMS[0] / 4, LVL_ELEMS[1] / 4, LVL_ELEMS[2] / 4,
                                       out);
}